// round 2
// baseline (speedup 1.0000x reference)
#include <cuda_runtime.h>
#include <cuda_bf16.h>
#include <math_constants.h>

// Problem constants (fixed by the dataset)
#define NN   50000
#define EE   800000
#define HIDD 128
#define HEADS 4
#define DH   32
#define NL   3
#define GG   64
#define LAT  64

using u64 = unsigned long long;

// ---------------------------------------------------------------------------
// Scratch (static __device__ arrays — no allocation anywhere)
// ---------------------------------------------------------------------------
__device__ float d_h[NN * HIDD];
__device__ float d_q[NN * HIDD];
__device__ float d_k[NN * HIDD];
__device__ float d_v[NN * HIDD];
__device__ float d_skip[NN * HIDD];
__device__ float d_pooled[GG * HIDD];

__device__ int d_deg[NN];
__device__ int d_rowptr[NN + 1];
__device__ int d_cursor[NN];
__device__ int d_csrsrc[EE];

// ---------------------------------------------------------------------------
// Packed f32x2 helpers (sm_100+): 2 FMAs per instruction on the fma pipe.
// ---------------------------------------------------------------------------
__device__ __forceinline__ u64 pack2(float lo, float hi) {
    u64 r;
    asm("mov.b64 %0, {%1, %2};" : "=l"(r) : "f"(lo), "f"(hi));
    return r;
}
__device__ __forceinline__ void fma2(u64& d, u64 a, u64 b) {
    asm("fma.rn.f32x2 %0, %1, %2, %0;" : "+l"(d) : "l"(a), "l"(b));
}
__device__ __forceinline__ float2 unpack2(u64 v) {
    float2 f;
    asm("mov.b64 {%0, %1}, %2;" : "=f"(f.x), "=f"(f.y) : "l"(v));
    return f;
}

// ---------------------------------------------------------------------------
// Zero init (graph-capture-safe, no symbol-address/memset host calls)
// ---------------------------------------------------------------------------
__global__ void k_zero() {
    int i = blockIdx.x * blockDim.x + threadIdx.x;
    if (i < NN) d_deg[i] = 0;
    if (i < GG * HIDD) d_pooled[i] = 0.f;
}

// ---------------------------------------------------------------------------
// CSR build: histogram -> scan -> scatter
// ---------------------------------------------------------------------------
__global__ void k_hist(const int* __restrict__ dst) {
    int e = blockIdx.x * blockDim.x + threadIdx.x;
    if (e < EE) atomicAdd(&d_deg[dst[e]], 1);
}

__global__ void k_scan() {
    __shared__ int sh[1024];
    __shared__ int s_carry;
    int tid = threadIdx.x;
    if (tid == 0) s_carry = 0;
    __syncthreads();
    for (int base = 0; base < NN; base += 1024) {
        int i = base + tid;
        int val = (i < NN) ? d_deg[i] : 0;
        sh[tid] = val;
        __syncthreads();
        for (int off = 1; off < 1024; off <<= 1) {
            int t = (tid >= off) ? sh[tid - off] : 0;
            __syncthreads();
            sh[tid] += t;
            __syncthreads();
        }
        int carry = s_carry;
        int excl = carry + sh[tid] - val;
        if (i < NN) { d_rowptr[i] = excl; d_cursor[i] = excl; }
        __syncthreads();
        if (tid == 1023) s_carry = carry + sh[1023];
        __syncthreads();
    }
    if (tid == 0) d_rowptr[NN] = s_carry;
}

__global__ void k_scatter(const int* __restrict__ src, const int* __restrict__ dst) {
    int e = blockIdx.x * blockDim.x + threadIdx.x;
    if (e < EE) {
        int p = atomicAdd(&d_cursor[dst[e]], 1);
        d_csrsrc[p] = src[e];
    }
}

// ---------------------------------------------------------------------------
// GEMM body (f32x2): C[m] = A @ W[m]^T + b[m]
//   A: [nrows,128] row-major, W: [128,128] row-major (out-major).
//   Block = 128 threads, 16 rows per block (50000 = 3125 * 16 exactly).
//   A tile transposed in smem (stride 20 floats keeps 16B alignment),
//   adjacent rows contiguous -> loaded as double2 and fed straight into
//   fma.rn.f32x2 as packed row pairs. W scalar broadcast-packed {w,w}.
//   NM matrices share every A-tile LDS (4x amortization for QKV+skip).
// ---------------------------------------------------------------------------
#define GROWS 16
#define ASTRIDE 20

template <int NM>
__device__ __forceinline__ void gemm_body(const float* __restrict__ A,
                                          const float* const* W,
                                          const float* const* b,
                                          float* const* C) {
    __shared__ float As[128 * ASTRIDE];
    const int tid = threadIdx.x;
    const int row0 = blockIdx.x * GROWS;

    // Load + transpose A tile: coalesced reads, scattered smem writes.
    #pragma unroll
    for (int it = 0; it < GROWS; ++it) {
        int idx = it * 128 + tid;          // 0..2047
        int r = idx >> 7;                  // local row 0..15
        int kcol = idx & 127;
        As[kcol * ASTRIDE + r] = A[(row0 + r) * 128 + kcol];
    }
    __syncthreads();

    const int o = tid;                     // output column 0..127
    u64 acc[2][NM][4];
    #pragma unroll
    for (int m = 0; m < NM; ++m) {
        float bb = b[m][o];
        u64 bp = pack2(bb, bb);
        #pragma unroll
        for (int c = 0; c < 2; ++c)
            #pragma unroll
            for (int p = 0; p < 4; ++p) acc[c][m][p] = bp;
    }

    const float4* W4[NM];
    #pragma unroll
    for (int m = 0; m < NM; ++m)
        W4[m] = reinterpret_cast<const float4*>(W[m] + o * 128);

    #pragma unroll 4
    for (int k4 = 0; k4 < 32; ++k4) {
        u64 wp[NM][4];
        #pragma unroll
        for (int m = 0; m < NM; ++m) {
            float4 w = W4[m][k4];          // L1-resident after first blocks
            wp[m][0] = pack2(w.x, w.x);
            wp[m][1] = pack2(w.y, w.y);
            wp[m][2] = pack2(w.z, w.z);
            wp[m][3] = pack2(w.w, w.w);
        }
        #pragma unroll
        for (int kk = 0; kk < 4; ++kk) {
            #pragma unroll
            for (int c = 0; c < 2; ++c) {
                const double2* ap = reinterpret_cast<const double2*>(
                    &As[(k4 * 4 + kk) * ASTRIDE + c * 8]);
                double2 d01 = ap[0];       // rows c*8+0..3 (two pairs)
                double2 d23 = ap[1];       // rows c*8+4..7
                u64 a0 = __double_as_longlong(d01.x);
                u64 a1 = __double_as_longlong(d01.y);
                u64 a2 = __double_as_longlong(d23.x);
                u64 a3 = __double_as_longlong(d23.y);
                #pragma unroll
                for (int m = 0; m < NM; ++m) {
                    fma2(acc[c][m][0], a0, wp[m][kk]);
                    fma2(acc[c][m][1], a1, wp[m][kk]);
                    fma2(acc[c][m][2], a2, wp[m][kk]);
                    fma2(acc[c][m][3], a3, wp[m][kk]);
                }
            }
        }
    }

    #pragma unroll
    for (int c = 0; c < 2; ++c)
        #pragma unroll
        for (int m = 0; m < NM; ++m)
            #pragma unroll
            for (int p = 0; p < 4; ++p) {
                float2 f = unpack2(acc[c][m][p]);
                int gr = row0 + c * 8 + p * 2;
                C[m][gr * 128 + o] = f.x;
                C[m][(gr + 1) * 128 + o] = f.y;
            }
}

__global__ __launch_bounds__(128)
void k_gemm_in(const float* __restrict__ x,
               const float* __restrict__ Win, const float* __restrict__ bin) {
    const float* W[1] = {Win};
    const float* b[1] = {bin};
    float* C[1] = {d_h};
    gemm_body<1>(x, W, b, C);
}

__global__ __launch_bounds__(128)
void k_gemm_qkvs(const float* __restrict__ Wq, const float* __restrict__ bq,
                 const float* __restrict__ Wk, const float* __restrict__ bk,
                 const float* __restrict__ Wv, const float* __restrict__ bv,
                 const float* __restrict__ Ws, const float* __restrict__ bs) {
    const float* W[4] = {Wq, Wk, Wv, Ws};
    const float* b[4] = {bq, bk, bv, bs};
    float* C[4] = {d_q, d_k, d_v, d_skip};
    gemm_body<4>(d_h, W, b, C);
}

// ---------------------------------------------------------------------------
// Fused attention: one warp per destination node, online softmax per head.
// lane l handles dims 4l..4l+3 (head = l/8); dot reduced over 8-lane groups.
// 2-edge unroll with combined pair update (one rescale, shared max).
// Writes h = relu(attn_out + skip). Last layer fuses global-add-pool.
// ---------------------------------------------------------------------------
template <bool POOL>
__global__ __launch_bounds__(256)
void k_attn(const int* __restrict__ batch) {
    int gw = (blockIdx.x * blockDim.x + threadIdx.x) >> 5;
    int lane = threadIdx.x & 31;
    if (gw >= NN) return;

    const float4* q4 = reinterpret_cast<const float4*>(d_q);
    const float4* k4 = reinterpret_cast<const float4*>(d_k);
    const float4* v4 = reinterpret_cast<const float4*>(d_v);
    const float4* s4 = reinterpret_cast<const float4*>(d_skip);
    float4* h4 = reinterpret_cast<float4*>(d_h);

    const float scale = 0.17677669529663687f; // 1/sqrt(32)
    float4 qq = q4[gw * 32 + lane];

    float m = -CUDART_INF_F;
    float s = 0.f;
    float4 acc = make_float4(0.f, 0.f, 0.f, 0.f);

    int beg = d_rowptr[gw];
    int end = d_rowptr[gw + 1];
    int i = beg;

    if ((end - beg) & 1) {   // odd tail first
        int src = d_csrsrc[i++];
        float4 kk = k4[src * 32 + lane];
        float4 vv = v4[src * 32 + lane];
        float part = qq.x * kk.x + qq.y * kk.y + qq.z * kk.z + qq.w * kk.w;
        part += __shfl_xor_sync(0xffffffffu, part, 1);
        part += __shfl_xor_sync(0xffffffffu, part, 2);
        part += __shfl_xor_sync(0xffffffffu, part, 4);
        float logit = part * scale;
        float nm = fmaxf(m, logit);
        float f = __expf(m - nm);
        float w = __expf(logit - nm);
        s = s * f + w;
        acc.x = acc.x * f + w * vv.x;
        acc.y = acc.y * f + w * vv.y;
        acc.z = acc.z * f + w * vv.z;
        acc.w = acc.w * f + w * vv.w;
        m = nm;
    }

    for (; i < end; i += 2) {
        int s0 = d_csrsrc[i];
        int s1 = d_csrsrc[i + 1];
        float4 k0 = k4[s0 * 32 + lane];
        float4 k1 = k4[s1 * 32 + lane];
        float4 v0 = v4[s0 * 32 + lane];
        float4 v1 = v4[s1 * 32 + lane];

        float p0 = qq.x * k0.x + qq.y * k0.y + qq.z * k0.z + qq.w * k0.w;
        float p1 = qq.x * k1.x + qq.y * k1.y + qq.z * k1.z + qq.w * k1.w;
        p0 += __shfl_xor_sync(0xffffffffu, p0, 1);
        p1 += __shfl_xor_sync(0xffffffffu, p1, 1);
        p0 += __shfl_xor_sync(0xffffffffu, p0, 2);
        p1 += __shfl_xor_sync(0xffffffffu, p1, 2);
        p0 += __shfl_xor_sync(0xffffffffu, p0, 4);
        p1 += __shfl_xor_sync(0xffffffffu, p1, 4);
        float l0 = p0 * scale;
        float l1 = p1 * scale;

        float nm = fmaxf(m, fmaxf(l0, l1));
        float f  = __expf(m - nm);
        float w0 = __expf(l0 - nm);
        float w1 = __expf(l1 - nm);
        s = s * f + w0 + w1;
        acc.x = acc.x * f + w0 * v0.x + w1 * v1.x;
        acc.y = acc.y * f + w0 * v0.y + w1 * v1.y;
        acc.z = acc.z * f + w0 * v0.z + w1 * v1.z;
        acc.w = acc.w * f + w0 * v0.w + w1 * v1.w;
        m = nm;
    }

    float inv = 1.f / (s + 1e-16f);
    float4 sk = s4[gw * 32 + lane];
    float4 o;
    o.x = fmaxf(acc.x * inv + sk.x, 0.f);
    o.y = fmaxf(acc.y * inv + sk.y, 0.f);
    o.z = fmaxf(acc.z * inv + sk.z, 0.f);
    o.w = fmaxf(acc.w * inv + sk.w, 0.f);

    if (POOL) {
        int g = batch[gw];
        float4* p4 = reinterpret_cast<float4*>(d_pooled);
        atomicAdd(&p4[g * 32 + lane], o);
    } else {
        h4[gw * 32 + lane] = o;
    }
}

// ---------------------------------------------------------------------------
// Final fc: out[g,o] = pooled[g,:] . Wfc[o,:] + bfc[o]
// ---------------------------------------------------------------------------
__global__ __launch_bounds__(64)
void k_fc(const float* __restrict__ Wfc, const float* __restrict__ bfc,
          float* __restrict__ out) {
    __shared__ float sp[128];
    int g = blockIdx.x;
    int o = threadIdx.x;
    for (int i = o; i < 128; i += 64) sp[i] = d_pooled[g * 128 + i];
    __syncthreads();
    float acc = bfc[o];
    #pragma unroll 8
    for (int kx = 0; kx < 128; ++kx) acc += sp[kx] * Wfc[o * 128 + kx];
    out[g * LAT + o] = acc;
}

// ---------------------------------------------------------------------------
// Launch
// ---------------------------------------------------------------------------
extern "C" void kernel_launch(void* const* d_in, const int* in_sizes, int n_in,
                              void* d_out, int out_size) {
    const float* x     = (const float*)d_in[0];
    const int*   ei    = (const int*)d_in[1];
    const int*   batch = (const int*)d_in[2];
    const float* Win   = (const float*)d_in[3];
    const float* bin_  = (const float*)d_in[4];
    const float* Wq    = (const float*)d_in[5];
    const float* bq    = (const float*)d_in[6];
    const float* Wk    = (const float*)d_in[7];
    const float* bk    = (const float*)d_in[8];
    const float* Wv    = (const float*)d_in[9];
    const float* bv    = (const float*)d_in[10];
    const float* Wsk   = (const float*)d_in[11];
    const float* bsk   = (const float*)d_in[12];
    const float* Wfc   = (const float*)d_in[13];
    const float* bfc   = (const float*)d_in[14];
    float* out = (float*)d_out;

    const int* src = ei;        // edge_index[0]
    const int* dst = ei + EE;   // edge_index[1]

    // ---- zero scratch + CSR build (every call; no caching allowed) ----
    k_zero<<<(NN + 255) / 256, 256>>>();
    k_hist<<<(EE + 255) / 256, 256>>>(dst);
    k_scan<<<1, 1024>>>();
    k_scatter<<<(EE + 255) / 256, 256>>>(src, dst);

    const int gemm_blocks = NN / GROWS;          // 3125, exact
    const int attn_blocks = (NN * 32 + 255) / 256;

    // ---- input projection ----
    k_gemm_in<<<gemm_blocks, 128>>>(x, Win, bin_);

    // ---- layers ----
    for (int l = 0; l < NL; ++l) {
        int wo = l * HIDD * HIDD;
        int bo = l * HIDD;
        k_gemm_qkvs<<<gemm_blocks, 128>>>(Wq + wo, bq + bo,
                                          Wk + wo, bk + bo,
                                          Wv + wo, bv + bo,
                                          Wsk + wo, bsk + bo);
        if (l == NL - 1)
            k_attn<true><<<attn_blocks, 256>>>(batch);   // fused global pool
        else
            k_attn<false><<<attn_blocks, 256>>>(batch);
    }

    // ---- fc ----
    k_fc<<<GG, 64>>>(Wfc, bfc, out);
}

// round 14
// speedup vs baseline: 1.0118x; 1.0118x over previous
#include <cuda_runtime.h>
#include <cuda_bf16.h>
#include <math_constants.h>
#include <cstdint>

// Problem constants (fixed by the dataset)
#define NN   50000
#define EE   800000
#define HIDD 128
#define HEADS 4
#define DH   32
#define NL   3
#define GG   64
#define LAT  64

using u64 = unsigned long long;

// ---------------------------------------------------------------------------
// Scratch (static __device__ arrays — no allocation anywhere)
// ---------------------------------------------------------------------------
__device__ float d_h[NN * HIDD];
__device__ float d_q[NN * HIDD];
__device__ float d_k[NN * HIDD];
__device__ float d_v[NN * HIDD];
__device__ float d_skip[NN * HIDD];
__device__ float d_pooled[GG * HIDD];

__device__ int d_deg[NN];
__device__ int d_rowptr[NN + 1];
__device__ int d_cursor[NN];
__device__ int d_csrsrc[EE];

// scan scratch
#define NBLK1 49
__device__ int d_scantmp[NN];
__device__ int d_blocksum[NBLK1];
__device__ int d_blockoff[NBLK1];

// ---------------------------------------------------------------------------
// Packed f32x2 helpers (sm_100+ base feature): 2 FMAs per fma-pipe instruction.
// ---------------------------------------------------------------------------
__device__ __forceinline__ u64 pack2(float lo, float hi) {
    u64 r;
    asm("mov.b64 %0, {%1, %2};" : "=l"(r) : "f"(lo), "f"(hi));
    return r;
}
__device__ __forceinline__ void fma2(u64& d, u64 a, u64 b) {
    asm("fma.rn.f32x2 %0, %1, %2, %0;" : "+l"(d) : "l"(a), "l"(b));
}
__device__ __forceinline__ float2 unpack2(u64 v) {
    float2 f;
    asm("mov.b64 {%0, %1}, %2;" : "=f"(f.x), "=f"(f.y) : "l"(v));
    return f;
}

// ---------------------------------------------------------------------------
// Zero init (graph-capture-safe)
// ---------------------------------------------------------------------------
__global__ void k_zero() {
    int i = blockIdx.x * blockDim.x + threadIdx.x;
    if (i < NN) d_deg[i] = 0;
    if (i < GG * HIDD) d_pooled[i] = 0.f;
}

// ---------------------------------------------------------------------------
// CSR build: histogram -> 3-kernel parallel scan -> scatter
// ---------------------------------------------------------------------------
__global__ void k_hist(const int* __restrict__ dst) {
    int e = blockIdx.x * blockDim.x + threadIdx.x;
    if (e < EE) atomicAdd(&d_deg[dst[e]], 1);
}

__global__ __launch_bounds__(1024) void k_scan1() {
    __shared__ int sh[1024];
    int tid = threadIdx.x;
    int i = blockIdx.x * 1024 + tid;
    int v = (i < NN) ? d_deg[i] : 0;
    sh[tid] = v;
    __syncthreads();
    for (int off = 1; off < 1024; off <<= 1) {
        int t = (tid >= off) ? sh[tid - off] : 0;
        __syncthreads();
        sh[tid] += t;
        __syncthreads();
    }
    if (i < NN) d_scantmp[i] = sh[tid] - v;       // exclusive within block
    if (tid == 1023) d_blocksum[blockIdx.x] = sh[1023];
}

__global__ void k_scan2() {
    __shared__ int sh[64];
    int t = threadIdx.x;
    int v = (t < NBLK1) ? d_blocksum[t] : 0;
    sh[t] = v;
    __syncthreads();
    for (int off = 1; off < 64; off <<= 1) {
        int x = (t >= off) ? sh[t - off] : 0;
        __syncthreads();
        sh[t] += x;
        __syncthreads();
    }
    if (t < NBLK1) d_blockoff[t] = sh[t] - v;
    if (t == NBLK1 - 1) d_rowptr[NN] = sh[t];
}

__global__ void k_scan3() {
    int i = blockIdx.x * blockDim.x + threadIdx.x;
    if (i < NN) {
        int e = d_scantmp[i] + d_blockoff[i >> 10];
        d_rowptr[i] = e;
        d_cursor[i] = e;
    }
}

__global__ void k_scatter(const int* __restrict__ src, const int* __restrict__ dst) {
    int e = blockIdx.x * blockDim.x + threadIdx.x;
    if (e < EE) {
        int p = atomicAdd(&d_cursor[dst[e]], 1);
        d_csrsrc[p] = src[e];
    }
}

// ---------------------------------------------------------------------------
// GEMM body (f32x2): C[m] = A @ W[m]^T + b[m]
//   A: [nrows,128] row-major, W: [128,128] row-major (out-major).
//   Block = 128 threads, 16 rows per block (50000 = 3125 * 16 exactly).
//   A tile transposed in smem (stride 20 floats; __align__(16) + offsets
//   80k+32c bytes keep every LDS.128 16B-aligned), adjacent rows contiguous
//   -> loaded as double2 and fed into fma.rn.f32x2 as packed row pairs.
//   W scalar broadcast-packed {w,w}. NM matrices share every A-tile LDS.
// ---------------------------------------------------------------------------
#define GROWS 16
#define ASTRIDE 20

template <int NM>
__device__ __forceinline__ void gemm_body(const float* __restrict__ A,
                                          const float* const* W,
                                          const float* const* b,
                                          float* const* C) {
    __shared__ __align__(16) float As[128 * ASTRIDE];
    const int tid = threadIdx.x;
    const int row0 = blockIdx.x * GROWS;

    // Load + transpose A tile: coalesced reads, scattered smem writes.
    #pragma unroll
    for (int it = 0; it < GROWS; ++it) {
        int idx = it * 128 + tid;          // 0..2047
        int r = idx >> 7;                  // local row 0..15
        int kcol = idx & 127;
        As[kcol * ASTRIDE + r] = A[(row0 + r) * 128 + kcol];
    }
    __syncthreads();

    const int o = tid;                     // output column 0..127
    u64 acc[2][NM][4];
    #pragma unroll
    for (int m = 0; m < NM; ++m) {
        float bb = b[m][o];
        u64 bp = pack2(bb, bb);
        #pragma unroll
        for (int c = 0; c < 2; ++c)
            #pragma unroll
            for (int p = 0; p < 4; ++p) acc[c][m][p] = bp;
    }

    const float4* W4[NM];
    #pragma unroll
    for (int m = 0; m < NM; ++m)
        W4[m] = reinterpret_cast<const float4*>(W[m] + o * 128);

    #pragma unroll 4
    for (int k4 = 0; k4 < 32; ++k4) {
        u64 wp[NM][4];
        #pragma unroll
        for (int m = 0; m < NM; ++m) {
            float4 w = W4[m][k4];          // L1/L2-resident after first blocks
            wp[m][0] = pack2(w.x, w.x);
            wp[m][1] = pack2(w.y, w.y);
            wp[m][2] = pack2(w.z, w.z);
            wp[m][3] = pack2(w.w, w.w);
        }
        #pragma unroll
        for (int kk = 0; kk < 4; ++kk) {
            #pragma unroll
            for (int c = 0; c < 2; ++c) {
                const double2* ap = reinterpret_cast<const double2*>(
                    &As[(k4 * 4 + kk) * ASTRIDE + c * 8]);
                double2 d01 = ap[0];       // rows c*8+0..3 (two packed pairs)
                double2 d23 = ap[1];       // rows c*8+4..7
                u64 a0 = __double_as_longlong(d01.x);
                u64 a1 = __double_as_longlong(d01.y);
                u64 a2 = __double_as_longlong(d23.x);
                u64 a3 = __double_as_longlong(d23.y);
                #pragma unroll
                for (int m = 0; m < NM; ++m) {
                    fma2(acc[c][m][0], a0, wp[m][kk]);
                    fma2(acc[c][m][1], a1, wp[m][kk]);
                    fma2(acc[c][m][2], a2, wp[m][kk]);
                    fma2(acc[c][m][3], a3, wp[m][kk]);
                }
            }
        }
    }

    #pragma unroll
    for (int c = 0; c < 2; ++c)
        #pragma unroll
        for (int m = 0; m < NM; ++m)
            #pragma unroll
            for (int p = 0; p < 4; ++p) {
                float2 f = unpack2(acc[c][m][p]);
                int gr = row0 + c * 8 + p * 2;
                C[m][gr * 128 + o] = f.x;
                C[m][(gr + 1) * 128 + o] = f.y;
            }
}

__global__ __launch_bounds__(128)
void k_gemm_in(const float* __restrict__ x,
               const float* __restrict__ Win, const float* __restrict__ bin) {
    const float* W[1] = {Win};
    const float* b[1] = {bin};
    float* C[1] = {d_h};
    gemm_body<1>(x, W, b, C);
}

__global__ __launch_bounds__(128)
void k_gemm_qkvs(const float* __restrict__ Wq, const float* __restrict__ bq,
                 const float* __restrict__ Wk, const float* __restrict__ bk,
                 const float* __restrict__ Wv, const float* __restrict__ bv,
                 const float* __restrict__ Ws, const float* __restrict__ bs) {
    const float* W[4] = {Wq, Wk, Wv, Ws};
    const float* b[4] = {bq, bk, bv, bs};
    float* C[4] = {d_q, d_k, d_v, d_skip};
    gemm_body<4>(d_h, W, b, C);
}

// ---------------------------------------------------------------------------
// Fused attention: one warp per destination node, online softmax per head.
// lane l handles dims 4l..4l+3 (head = l/8); dot reduced over 8-lane groups.
// 2-edge unroll with combined pair update (one rescale, shared max).
// Writes h = relu(attn_out + skip). Last layer fuses global-add-pool.
// ---------------------------------------------------------------------------
template <bool POOL>
__global__ __launch_bounds__(256)
void k_attn(const int* __restrict__ batch) {
    int gw = (blockIdx.x * blockDim.x + threadIdx.x) >> 5;
    int lane = threadIdx.x & 31;
    if (gw >= NN) return;

    const float4* q4 = reinterpret_cast<const float4*>(d_q);
    const float4* k4 = reinterpret_cast<const float4*>(d_k);
    const float4* v4 = reinterpret_cast<const float4*>(d_v);
    const float4* s4 = reinterpret_cast<const float4*>(d_skip);
    float4* h4 = reinterpret_cast<float4*>(d_h);

    const float scale = 0.17677669529663687f; // 1/sqrt(32)
    float4 qq = q4[gw * 32 + lane];

    float m = -CUDART_INF_F;
    float s = 0.f;
    float4 acc = make_float4(0.f, 0.f, 0.f, 0.f);

    int beg = d_rowptr[gw];
    int end = d_rowptr[gw + 1];
    int i = beg;

    if ((end - beg) & 1) {   // odd tail first
        int src = d_csrsrc[i++];
        float4 kk = k4[src * 32 + lane];
        float4 vv = v4[src * 32 + lane];
        float part = qq.x * kk.x + qq.y * kk.y + qq.z * kk.z + qq.w * kk.w;
        part += __shfl_xor_sync(0xffffffffu, part, 1);
        part += __shfl_xor_sync(0xffffffffu, part, 2);
        part += __shfl_xor_sync(0xffffffffu, part, 4);
        float logit = part * scale;
        float nm = fmaxf(m, logit);
        float f = __expf(m - nm);
        float w = __expf(logit - nm);
        s = s * f + w;
        acc.x = acc.x * f + w * vv.x;
        acc.y = acc.y * f + w * vv.y;
        acc.z = acc.z * f + w * vv.z;
        acc.w = acc.w * f + w * vv.w;
        m = nm;
    }

    for (; i < end; i += 2) {
        int s0 = d_csrsrc[i];
        int s1 = d_csrsrc[i + 1];
        float4 k0 = k4[s0 * 32 + lane];
        float4 k1 = k4[s1 * 32 + lane];
        float4 v0 = v4[s0 * 32 + lane];
        float4 v1 = v4[s1 * 32 + lane];

        float p0 = qq.x * k0.x + qq.y * k0.y + qq.z * k0.z + qq.w * k0.w;
        float p1 = qq.x * k1.x + qq.y * k1.y + qq.z * k1.z + qq.w * k1.w;
        p0 += __shfl_xor_sync(0xffffffffu, p0, 1);
        p1 += __shfl_xor_sync(0xffffffffu, p1, 1);
        p0 += __shfl_xor_sync(0xffffffffu, p0, 2);
        p1 += __shfl_xor_sync(0xffffffffu, p1, 2);
        p0 += __shfl_xor_sync(0xffffffffu, p0, 4);
        p1 += __shfl_xor_sync(0xffffffffu, p1, 4);
        float l0 = p0 * scale;
        float l1 = p1 * scale;

        float nm = fmaxf(m, fmaxf(l0, l1));
        float f  = __expf(m - nm);
        float w0 = __expf(l0 - nm);
        float w1 = __expf(l1 - nm);
        s = s * f + w0 + w1;
        acc.x = acc.x * f + w0 * v0.x + w1 * v1.x;
        acc.y = acc.y * f + w0 * v0.y + w1 * v1.y;
        acc.z = acc.z * f + w0 * v0.z + w1 * v1.z;
        acc.w = acc.w * f + w0 * v0.w + w1 * v1.w;
        m = nm;
    }

    float inv = 1.f / (s + 1e-16f);
    float4 sk = s4[gw * 32 + lane];
    float4 o;
    o.x = fmaxf(acc.x * inv + sk.x, 0.f);
    o.y = fmaxf(acc.y * inv + sk.y, 0.f);
    o.z = fmaxf(acc.z * inv + sk.z, 0.f);
    o.w = fmaxf(acc.w * inv + sk.w, 0.f);

    if (POOL) {
        int g = batch[gw];
        float4* p4 = reinterpret_cast<float4*>(d_pooled);
        atomicAdd(&p4[g * 32 + lane], o);
    } else {
        h4[gw * 32 + lane] = o;
    }
}

// ---------------------------------------------------------------------------
// Final fc: out[g,o] = pooled[g,:] . Wfc[o,:] + bfc[o]
// ---------------------------------------------------------------------------
__global__ __launch_bounds__(64)
void k_fc(const float* __restrict__ Wfc, const float* __restrict__ bfc,
          float* __restrict__ out) {
    __shared__ float sp[128];
    int g = blockIdx.x;
    int o = threadIdx.x;
    for (int i = o; i < 128; i += 64) sp[i] = d_pooled[g * 128 + i];
    __syncthreads();
    float acc = bfc[o];
    #pragma unroll 8
    for (int kx = 0; kx < 128; ++kx) acc += sp[kx] * Wfc[o * 128 + kx];
    out[g * LAT + o] = acc;
}

// ---------------------------------------------------------------------------
// Launch
// ---------------------------------------------------------------------------
extern "C" void kernel_launch(void* const* d_in, const int* in_sizes, int n_in,
                              void* d_out, int out_size) {
    const float* x     = (const float*)d_in[0];
    const int*   ei    = (const int*)d_in[1];
    const int*   batch = (const int*)d_in[2];
    const float* Win   = (const float*)d_in[3];
    const float* bin_  = (const float*)d_in[4];
    const float* Wq    = (const float*)d_in[5];
    const float* bq    = (const float*)d_in[6];
    const float* Wk    = (const float*)d_in[7];
    const float* bk    = (const float*)d_in[8];
    const float* Wv    = (const float*)d_in[9];
    const float* bv    = (const float*)d_in[10];
    const float* Wsk   = (const float*)d_in[11];
    const float* bsk   = (const float*)d_in[12];
    const float* Wfc   = (const float*)d_in[13];
    const float* bfc   = (const float*)d_in[14];
    float* out = (float*)d_out;

    const int* src = ei;        // edge_index[0]
    const int* dst = ei + EE;   // edge_index[1]

    // ---- zero scratch + CSR build (every call; no caching allowed) ----
    k_zero<<<(NN + 255) / 256, 256>>>();
    k_hist<<<(EE + 255) / 256, 256>>>(dst);
    k_scan1<<<NBLK1, 1024>>>();
    k_scan2<<<1, 64>>>();
    k_scan3<<<(NN + 255) / 256, 256>>>();
    k_scatter<<<(EE + 255) / 256, 256>>>(src, dst);

    const int gemm_blocks = NN / GROWS;          // 3125, exact
    const int attn_blocks = (NN * 32 + 255) / 256;

    // ---- input projection ----
    k_gemm_in<<<gemm_blocks, 128>>>(x, Win, bin_);

    // ---- layers ----
    for (int l = 0; l < NL; ++l) {
        int wo = l * HIDD * HIDD;
        int bo = l * HIDD;
        k_gemm_qkvs<<<gemm_blocks, 128>>>(Wq + wo, bq + bo,
                                          Wk + wo, bk + bo,
                                          Wv + wo, bv + bo,
                                          Wsk + wo, bsk + bo);
        if (l == NL - 1)
            k_attn<true><<<attn_blocks, 256>>>(batch);   // fused global pool
        else
            k_attn<false><<<attn_blocks, 256>>>(batch);
    }

    // ---- fc ----
    k_fc<<<GG, 64>>>(Wfc, bfc, out);
}